// round 1
// baseline (speedup 1.0000x reference)
#include <cuda_runtime.h>
#include <cstdint>

// Problem constants
#define B_  32
#define T_  1000
#define I_  3
#define R_  2048
#define O_  3

#define CAP     160          // per-row nnz capacity (mean ~41, P(>160) ~ 0)
#define GRID    128          // persistent CTAs (<= 148 SMs -> all co-resident)
#define RPC     16           // rows per CTA (128*16 = 2048)
#define NTHR    512          // 16 warps, warp-per-row

// ---------------- device scratch (no allocs allowed) ----------------
__device__ float    g_state[2][R_ * B_];          // double-buffered state, [r][b]
__device__ unsigned g_cols[R_][CAP];              // pre-multiplied by B_
__device__ float    g_vals[R_][CAP];
__device__ int      g_cnt[R_];                    // padded to multiple of 8
__device__ unsigned g_sync;

// ---------------- helpers ----------------
__device__ __forceinline__ unsigned ld_acq(const unsigned* p) {
    unsigned v;
    asm volatile("ld.acquire.gpu.u32 %0, [%1];" : "=r"(v) : "l"(p) : "memory");
    return v;
}

// ---------------- P1: sparse compaction + init ----------------
// One block (32 threads) per row. Deterministic ordered compaction via ballot.
__global__ void prep_kernel(const float* __restrict__ W) {
    int r = blockIdx.x;
    int lane = threadIdx.x;
    const float* row = W + (size_t)r * R_;

    int base = 0;
    for (int c0 = 0; c0 < R_; c0 += 32) {
        float v = row[c0 + lane];
        unsigned m = __ballot_sync(0xffffffffu, v != 0.0f);
        if (v != 0.0f) {
            int off = __popc(m & ((1u << lane) - 1u));
            int p = base + off;
            if (p < CAP) {
                g_cols[r][p] = (unsigned)(c0 + lane) * B_;  // pre-scaled gather index
                g_vals[r][p] = v;
            }
        }
        base += __popc(m);
    }
    if (base > CAP) base = CAP;
    int padded = (base + 7) & ~7;
    if (padded > CAP) padded = CAP;
    for (int p = base + lane; p < padded; p += 32) {
        g_cols[r][p] = 0u;
        g_vals[r][p] = 0.0f;
    }
    if (lane == 0) g_cnt[r] = padded;

    // zero initial state (buf 0) -- must happen every launch (graph replay)
    g_state[0][r * B_ + lane] = 0.0f;
    if (r == 0 && lane == 0) g_sync = 0u;
}

// ---------------- P2: persistent recurrence ----------------
__global__ void __launch_bounds__(NTHR, 1)
esn_kernel(const float* __restrict__ x,        // [B,T,I]
           const float* __restrict__ win,      // [R,I]
           const float* __restrict__ noise,    // [B,R]
           float* __restrict__ states_out) {   // [B,T,R]
    __shared__ uint2 snnz[RPC][CAP];           // (col*B, val bits)  20 KB
    __shared__ float tile[RPC][B_ + 1];        // staged outputs for transpose
    __shared__ float xs[B_][4];                // x_t per batch

    const int tid  = threadIdx.x;
    const int w    = tid >> 5;                 // warp = local row
    const int lane = tid & 31;                 // lane = batch
    const int rbase = blockIdx.x * RPC;
    const int r = rbase + w;

    // preload sparse row into SMEM (reused for all 1000 steps)
    const int cnt = g_cnt[r];
    for (int k = lane; k < cnt; k += 32)
        snnz[w][k] = make_uint2(g_cols[r][k], __float_as_uint(g_vals[r][k]));

    // per-thread constants
    const float nz = noise[(size_t)lane * R_ + r];
    const float w0 = win[r * 3 + 0];
    const float w1 = win[r * 3 + 1];
    const float w2 = win[r * 3 + 2];

    __syncthreads();

    unsigned target = 0;
    for (int t = 0; t < T_; t++) {
        const float* cur = &g_state[t & 1][0];
        float* nxt       = &g_state[(t + 1) & 1][0];

        // stage x_t into SMEM: threads 0..95 each load one (b,i)
        if (tid < B_ * I_) {
            int b = tid / 3, i = tid - b * 3;
            xs[b][i] = x[(size_t)b * (T_ * I_) + t * I_ + i];
        }
        __syncthreads();

        float acc = fmaf(w0, xs[lane][0],
                    fmaf(w1, xs[lane][1],
                    fmaf(w2, xs[lane][2], nz)));

        // sparse gather: cnt padded to multiple of 8; unroll 4 for MLP
        #pragma unroll 2
        for (int k = 0; k < cnt; k += 4) {
            uint2 e0 = snnz[w][k + 0];
            uint2 e1 = snnz[w][k + 1];
            uint2 e2 = snnz[w][k + 2];
            uint2 e3 = snnz[w][k + 3];
            float s0 = __ldcg(cur + e0.x + lane);   // L2-only: L1 is stale across SMs
            float s1 = __ldcg(cur + e1.x + lane);
            float s2 = __ldcg(cur + e2.x + lane);
            float s3 = __ldcg(cur + e3.x + lane);
            acc = fmaf(__uint_as_float(e0.y), s0, acc);
            acc = fmaf(__uint_as_float(e1.y), s1, acc);
            acc = fmaf(__uint_as_float(e2.y), s2, acc);
            acc = fmaf(__uint_as_float(e3.y), s3, acc);
        }

        float s = tanhf(acc);

        nxt[r * B_ + lane] = s;       // 128B coalesced per warp
        tile[w][lane] = s;
        __syncthreads();

        // transpose write of states[b][t][rbase..rbase+15]:
        // each half-warp writes 16 contiguous floats (64B) for one batch
        {
            int b  = w + ((lane >> 4) << 4);   // w or w+16
            int rr = lane & 15;
            states_out[(size_t)b * (T_ * R_) + (size_t)t * R_ + rbase + rr] = tile[rr][b];
        }

        // ---- grid-wide epoch sync ----
        __threadfence();
        __syncthreads();
        target += GRID;
        if (tid == 0) {
            atomicAdd(&g_sync, 1u);
            while (ld_acq(&g_sync) < target) { }
        }
        __syncthreads();
    }
}

// ---------------- P3: output projection  out[b][o] = sum_r s[r][b]*Wout[o][r]
__global__ void outproj_kernel(const float* __restrict__ wout,  // [O,R]
                               float* __restrict__ out) {       // [B*O]
    __shared__ float red[256];
    int pair = blockIdx.x;            // 0..95
    int b = pair / O_, o = pair - b * O_;
    const float* st = &g_state[0][0]; // final state lands in buf 0 (T even)

    float sum = 0.0f;
    for (int r = threadIdx.x; r < R_; r += blockDim.x)
        sum += st[r * B_ + b] * wout[o * R_ + r];

    red[threadIdx.x] = sum;
    __syncthreads();
    for (int s = 128; s > 0; s >>= 1) {
        if (threadIdx.x < s) red[threadIdx.x] += red[threadIdx.x + s];
        __syncthreads();
    }
    if (threadIdx.x == 0) out[b * O_ + o] = red[0];
}

// ---------------- launch ----------------
extern "C" void kernel_launch(void* const* d_in, const int* in_sizes, int n_in,
                              void* d_out, int out_size) {
    (void)in_sizes; (void)n_in; (void)out_size;
    const float* x     = (const float*)d_in[0];   // [B,T,I]
    const float* win   = (const float*)d_in[1];   // [R,I]
    const float* wres  = (const float*)d_in[2];   // [R,R]
    const float* wout  = (const float*)d_in[3];   // [O,R]
    const float* noise = (const float*)d_in[4];   // [B,R]
    float* out = (float*)d_out;                   // [B*O] then [B,T,R]

    prep_kernel<<<R_, 32>>>(wres);
    esn_kernel<<<GRID, NTHR>>>(x, win, noise, out + B_ * O_);
    outproj_kernel<<<B_ * O_, 256>>>(wout, out);
}

// round 2
// speedup vs baseline: 1.2294x; 1.2294x over previous
#include <cuda_runtime.h>
#include <cstdint>

// Problem constants
#define B_  32
#define T_  1000
#define I_  3
#define R_  2048
#define O_  3

#define CAP     160          // per-row nnz capacity (mean ~41)
#define GRID    128          // persistent CTAs (all co-resident)
#define RPC     16           // rows per CTA
#define NTHR    512          // 16 warps, warp-per-row

// ---------------- device scratch ----------------
__device__ float             g_state[2][R_ * B_];     // double-buffered state [r][b]
__device__ unsigned          g_cols[R_][CAP];         // col*B_
__device__ float             g_vals[R_][CAP];
__device__ int               g_cnt[R_];               // padded to multiple of 8
__device__ volatile unsigned g_flag[GRID * 32];       // one 128B line per CTA

// ---------------- P1: sparse compaction + init ----------------
__global__ void prep_kernel(const float* __restrict__ W) {
    int r = blockIdx.x;
    int lane = threadIdx.x;
    const float* row = W + (size_t)r * R_;

    int base = 0;
    for (int c0 = 0; c0 < R_; c0 += 32) {
        float v = row[c0 + lane];
        unsigned m = __ballot_sync(0xffffffffu, v != 0.0f);
        if (v != 0.0f) {
            int off = __popc(m & ((1u << lane) - 1u));
            int p = base + off;
            if (p < CAP) {
                g_cols[r][p] = (unsigned)(c0 + lane) * B_;
                g_vals[r][p] = v;
            }
        }
        base += __popc(m);
    }
    if (base > CAP) base = CAP;
    int padded = (base + 7) & ~7;
    if (padded > CAP) padded = CAP;
    for (int p = base + lane; p < padded; p += 32) {
        g_cols[r][p] = 0u;
        g_vals[r][p] = 0.0f;
    }
    if (lane == 0) g_cnt[r] = padded;

    // reset per-launch mutable state (graph replay safe)
    g_state[0][r * B_ + lane] = 0.0f;
    if (r < GRID && lane == 0) g_flag[r << 5] = 0u;
}

// ---------------- P2: persistent recurrence ----------------
__global__ void __launch_bounds__(NTHR, 1)
esn_kernel(const float* __restrict__ x,        // [B,T,I]
           const float* __restrict__ win,      // [R,I]
           const float* __restrict__ noise,    // [B,R]
           float* __restrict__ states_out) {   // [B,T,R]
    __shared__ uint2 snnz[RPC][CAP];           // (col*B, val bits)  20 KB
    __shared__ float tile[RPC][B_ + 1];        // staged outputs for transpose
    __shared__ float xs[B_][4];                // x_t per batch

    const int tid  = threadIdx.x;
    const int w    = tid >> 5;                 // warp = local row
    const int lane = tid & 31;                 // lane = batch
    const int rbase = blockIdx.x * RPC;
    const int r = rbase + w;

    // preload sparse row into SMEM (reused for all 1000 steps)
    const int cnt = g_cnt[r];
    for (int k = lane; k < cnt; k += 32)
        snnz[w][k] = make_uint2(g_cols[r][k], __float_as_uint(g_vals[r][k]));

    // per-thread constants
    const float nz = noise[(size_t)lane * R_ + r];
    const float w0 = win[r * 3 + 0];
    const float w1 = win[r * 3 + 1];
    const float w2 = win[r * 3 + 2];

    // stage x for t=0
    if (tid < B_ * I_) {
        int b = tid / 3, i = tid - b * 3;
        xs[b][i] = x[(size_t)b * (T_ * I_) + i];
    }
    __syncthreads();

    for (int t = 0; t < T_; t++) {
        const float* cur = &g_state[t & 1][0];
        float* nxt       = &g_state[(t + 1) & 1][0];

        float acc = fmaf(w0, xs[lane][0],
                    fmaf(w1, xs[lane][1],
                    fmaf(w2, xs[lane][2], nz)));

        // sparse gather: cnt padded to multiple of 8; 8 loads in flight
        for (int k = 0; k < cnt; k += 8) {
            uint2 e0 = snnz[w][k + 0];
            uint2 e1 = snnz[w][k + 1];
            uint2 e2 = snnz[w][k + 2];
            uint2 e3 = snnz[w][k + 3];
            uint2 e4 = snnz[w][k + 4];
            uint2 e5 = snnz[w][k + 5];
            uint2 e6 = snnz[w][k + 6];
            uint2 e7 = snnz[w][k + 7];
            float s0 = __ldcg(cur + e0.x + lane);   // L2-only (L1 stale across SMs)
            float s1 = __ldcg(cur + e1.x + lane);
            float s2 = __ldcg(cur + e2.x + lane);
            float s3 = __ldcg(cur + e3.x + lane);
            float s4 = __ldcg(cur + e4.x + lane);
            float s5 = __ldcg(cur + e5.x + lane);
            float s6 = __ldcg(cur + e6.x + lane);
            float s7 = __ldcg(cur + e7.x + lane);
            acc = fmaf(__uint_as_float(e0.y), s0, acc);
            acc = fmaf(__uint_as_float(e1.y), s1, acc);
            acc = fmaf(__uint_as_float(e2.y), s2, acc);
            acc = fmaf(__uint_as_float(e3.y), s3, acc);
            acc = fmaf(__uint_as_float(e4.y), s4, acc);
            acc = fmaf(__uint_as_float(e5.y), s5, acc);
            acc = fmaf(__uint_as_float(e6.y), s6, acc);
            acc = fmaf(__uint_as_float(e7.y), s7, acc);
        }

        float s = tanhf(acc);

        nxt[r * B_ + lane] = s;       // 128B coalesced per warp
        tile[w][lane] = s;
        __syncthreads();              // all state/tile writes done

        // ---- arrival: make state visible, raise this CTA's flag ----
        if (tid == 0) {
            __threadfence();
            g_flag[blockIdx.x << 5] = (unsigned)(t + 1);
        }

        // ---- off-critical-path work while others arrive ----
        // transposed states write: half-warp writes 64B contiguous per batch
        {
            int b  = w + ((lane >> 4) << 4);   // w or w+16
            int rr = lane & 15;
            states_out[(size_t)b * (T_ * R_) + (size_t)t * R_ + rbase + rr] = tile[rr][b];
        }
        // stage x for t+1
        if (t + 1 < T_ && tid < B_ * I_) {
            int b = tid / 3, i = tid - b * 3;
            xs[b][i] = x[(size_t)b * (T_ * I_) + (t + 1) * I_ + i];
        }

        // ---- wait: 128 threads poll 128 distinct flag lines ----
        if (tid < GRID) {
            while (g_flag[tid << 5] < (unsigned)(t + 1)) { }
        }
        __syncthreads();
    }
}

// ---------------- P3: output projection ----------------
__global__ void outproj_kernel(const float* __restrict__ wout,  // [O,R]
                               float* __restrict__ out) {       // [B*O]
    __shared__ float red[256];
    int pair = blockIdx.x;            // 0..95
    int b = pair / O_, o = pair - b * O_;
    const float* st = &g_state[0][0]; // T even -> final state in buf 0

    float sum = 0.0f;
    for (int r = threadIdx.x; r < R_; r += blockDim.x)
        sum += st[r * B_ + b] * wout[o * R_ + r];

    red[threadIdx.x] = sum;
    __syncthreads();
    for (int s = 128; s > 0; s >>= 1) {
        if (threadIdx.x < s) red[threadIdx.x] += red[threadIdx.x + s];
        __syncthreads();
    }
    if (threadIdx.x == 0) out[b * O_ + o] = red[0];
}

// ---------------- launch ----------------
extern "C" void kernel_launch(void* const* d_in, const int* in_sizes, int n_in,
                              void* d_out, int out_size) {
    (void)in_sizes; (void)n_in; (void)out_size;
    const float* x     = (const float*)d_in[0];   // [B,T,I]
    const float* win   = (const float*)d_in[1];   // [R,I]
    const float* wres  = (const float*)d_in[2];   // [R,R]
    const float* wout  = (const float*)d_in[3];   // [O,R]
    const float* noise = (const float*)d_in[4];   // [B,R]
    float* out = (float*)d_out;                   // [B*O] then [B,T,R]

    prep_kernel<<<R_, 32>>>(wres);
    esn_kernel<<<GRID, NTHR>>>(x, win, noise, out + B_ * O_);
    outproj_kernel<<<B_ * O_, 256>>>(wout, out);
}

// round 3
// speedup vs baseline: 1.5328x; 1.2468x over previous
#include <cuda_runtime.h>
#include <cstdint>

// Problem constants
#define B_  32
#define T_  1000
#define I_  3
#define R_  2048
#define O_  3

#define CAP     160          // per-row nnz capacity (mean ~41, max ~72, padded to mult of 16)
#define GRID    128          // persistent CTAs (all co-resident)
#define RPC     16           // rows per CTA
#define NTHR    512          // 16 warps, warp-per-row

// ---------------- device scratch ----------------
__device__ float             g_state[2][R_ * B_];     // double-buffered state [r][b]
__device__ unsigned          g_cols[R_][CAP];         // col*B_
__device__ float             g_vals[R_][CAP];
__device__ int               g_cnt[R_];               // padded to multiple of 16, >=16
__device__ volatile unsigned g_flag[GRID * 32];       // one 128B line per CTA

// ---------------- P1: sparse compaction + init ----------------
__global__ void prep_kernel(const float* __restrict__ W) {
    int r = blockIdx.x;
    int lane = threadIdx.x;
    const float* row = W + (size_t)r * R_;

    int base = 0;
    for (int c0 = 0; c0 < R_; c0 += 32) {
        float v = row[c0 + lane];
        unsigned m = __ballot_sync(0xffffffffu, v != 0.0f);
        if (v != 0.0f) {
            int off = __popc(m & ((1u << lane) - 1u));
            int p = base + off;
            if (p < CAP) {
                g_cols[r][p] = (unsigned)(c0 + lane) * B_;
                g_vals[r][p] = v;
            }
        }
        base += __popc(m);
    }
    if (base > CAP) base = CAP;
    int padded = (base + 15) & ~15;
    if (padded < 16) padded = 16;
    if (padded > CAP) padded = CAP;
    // pad with val=0 entries whose cols are spread across distinct lines
    for (int p = base + lane; p < padded; p += 32) {
        g_cols[r][p] = ((unsigned)(r * 7 + p * 13) & (R_ - 1)) * B_;
        g_vals[r][p] = 0.0f;
    }
    if (lane == 0) g_cnt[r] = padded;

    // reset per-launch mutable state (graph replay safe)
    g_state[0][r * B_ + lane] = 0.0f;
    if (r < GRID && lane == 0) g_flag[r << 5] = 0u;
}

// ---------------- P2: persistent recurrence ----------------
__global__ void __launch_bounds__(NTHR, 1)
esn_kernel(const float* __restrict__ x,        // [B,T,I]
           const float* __restrict__ win,      // [R,I]
           const float* __restrict__ noise,    // [B,R]
           float* __restrict__ states_out) {   // [B,T,R]
    __shared__ uint2 snnz[RPC][CAP];           // (col*B, val bits)  20 KB
    __shared__ float tile[RPC][B_ + 1];        // staged outputs for transpose
    __shared__ float xs[B_][4];                // x_t per batch

    const int tid  = threadIdx.x;
    const int w    = tid >> 5;                 // warp = local row
    const int lane = tid & 31;                 // lane = batch
    const int rbase = blockIdx.x * RPC;
    const int r = rbase + w;

    // preload sparse row into SMEM (reused for all 1000 steps)
    const int cnt = g_cnt[r];
    for (int k = lane; k < cnt; k += 32)
        snnz[w][k] = make_uint2(g_cols[r][k], __float_as_uint(g_vals[r][k]));

    // per-thread constants
    const float nz = noise[(size_t)lane * R_ + r];
    const float w0 = win[r * 3 + 0];
    const float w1 = win[r * 3 + 1];
    const float w2 = win[r * 3 + 2];

    // stage x for t=0
    if (tid < B_ * I_) {
        int b = tid / 3, i = tid - b * 3;
        xs[b][i] = x[(size_t)b * (T_ * I_) + i];
    }
    __syncthreads();

    for (int t = 0; t < T_; t++) {
        const float* cur = &g_state[t & 1][0];
        float* nxt       = &g_state[(t + 1) & 1][0];

        float acc0 = fmaf(w0, xs[lane][0],
                     fmaf(w1, xs[lane][1],
                     fmaf(w2, xs[lane][2], nz)));
        float acc1 = 0.0f;

        // ---- software-pipelined sparse gather (16-nnz chunks, ping-pong) ----
        float sA[16], vA[16], sB[16], vB[16];

        auto load16 = [&](float* s, float* v, int base_) {
            #pragma unroll
            for (int j = 0; j < 16; j++) {
                uint2 e = snnz[w][base_ + j];
                v[j] = __uint_as_float(e.y);
                s[j] = __ldcg(cur + e.x + lane);   // L2-only (L1 stale across SMs)
            }
        };
        auto consume16 = [&](const float* s, const float* v) {
            #pragma unroll
            for (int j = 0; j < 16; j += 2) {
                acc0 = fmaf(v[j],     s[j],     acc0);
                acc1 = fmaf(v[j + 1], s[j + 1], acc1);
            }
        };

        load16(sA, vA, 0);
        for (int k = 16; k < cnt; k += 32) {
            load16(sB, vB, k);          // chunk k in flight while chunk k-16 consumed
            consume16(sA, vA);
            if (k + 16 < cnt) load16(sA, vA, k + 16);
            consume16(sB, vB);
        }
        if ((cnt >> 4) & 1) consume16(sA, vA);  // odd #chunks -> pending A

        float s = tanhf(acc0 + acc1);

        nxt[r * B_ + lane] = s;       // 128B coalesced per warp
        tile[w][lane] = s;
        __syncthreads();              // all state/tile writes done

        // ---- arrival: make state visible, raise this CTA's flag ----
        if (tid == 0) {
            __threadfence();
            g_flag[blockIdx.x << 5] = (unsigned)(t + 1);
        }

        // ---- off-critical-path work while others arrive ----
        {   // transposed states write: half-warp writes 64B contiguous per batch
            int b  = w + ((lane >> 4) << 4);   // w or w+16
            int rr = lane & 15;
            states_out[(size_t)b * (T_ * R_) + (size_t)t * R_ + rbase + rr] = tile[rr][b];
        }
        if (t + 1 < T_ && tid < B_ * I_) {     // stage x for t+1
            int b = tid / 3, i = tid - b * 3;
            xs[b][i] = x[(size_t)b * (T_ * I_) + (t + 1) * I_ + i];
        }

        // ---- wait: 128 threads poll 128 distinct flag lines ----
        if (tid < GRID) {
            while (g_flag[tid << 5] < (unsigned)(t + 1)) { }
        }
        __syncthreads();
    }
}

// ---------------- P3: output projection ----------------
__global__ void outproj_kernel(const float* __restrict__ wout,  // [O,R]
                               float* __restrict__ out) {       // [B*O]
    __shared__ float red[256];
    int pair = blockIdx.x;            // 0..95
    int b = pair / O_, o = pair - b * O_;
    const float* st = &g_state[0][0]; // T even -> final state in buf 0

    float sum = 0.0f;
    for (int r = threadIdx.x; r < R_; r += blockDim.x)
        sum += st[r * B_ + b] * wout[o * R_ + r];

    red[threadIdx.x] = sum;
    __syncthreads();
    for (int s = 128; s > 0; s >>= 1) {
        if (threadIdx.x < s) red[threadIdx.x] += red[threadIdx.x + s];
        __syncthreads();
    }
    if (threadIdx.x == 0) out[b * O_ + o] = red[0];
}

// ---------------- launch ----------------
extern "C" void kernel_launch(void* const* d_in, const int* in_sizes, int n_in,
                              void* d_out, int out_size) {
    (void)in_sizes; (void)n_in; (void)out_size;
    const float* x     = (const float*)d_in[0];   // [B,T,I]
    const float* win   = (const float*)d_in[1];   // [R,I]
    const float* wres  = (const float*)d_in[2];   // [R,R]
    const float* wout  = (const float*)d_in[3];   // [O,R]
    const float* noise = (const float*)d_in[4];   // [B,R]
    float* out = (float*)d_out;                   // [B*O] then [B,T,R]

    prep_kernel<<<R_, 32>>>(wres);
    esn_kernel<<<GRID, NTHR>>>(x, win, noise, out + B_ * O_);
    outproj_kernel<<<B_ * O_, 256>>>(wout, out);
}

// round 4
// speedup vs baseline: 1.7092x; 1.1151x over previous
#include <cuda_runtime.h>
#include <cuda_fp16.h>
#include <cstdint>

// Problem constants
#define B_  32
#define T_  1000
#define I_  3
#define R_  2048
#define O_  3

#define CAP     160          // per-row nnz capacity (padded to mult of 16)
#define GRID    128          // persistent CTAs (all co-resident)
#define RPC     16           // rows per CTA
#define NTHR    512          // 16 warps, warp-per-row

// ---------------- device scratch ----------------
__device__ __half            g_state[2][R_ * B_];     // fp16 state, [r][b], 64B/row
__device__ float             g_final[R_ * B_];        // fp32 final state for outproj
__device__ unsigned          g_cols[R_][CAP];         // col * 16 (uint-word offset of row)
__device__ float             g_vals[R_][CAP];
__device__ int               g_cnt[R_];               // padded to multiple of 16, >=16
__device__ volatile unsigned g_flag[GRID * 32];       // one 128B line per CTA

// ---------------- P1: sparse compaction + init ----------------
__global__ void prep_kernel(const float* __restrict__ W) {
    int r = blockIdx.x;
    int lane = threadIdx.x;
    const float* row = W + (size_t)r * R_;

    int base = 0;
    for (int c0 = 0; c0 < R_; c0 += 32) {
        float v = row[c0 + lane];
        unsigned m = __ballot_sync(0xffffffffu, v != 0.0f);
        if (v != 0.0f) {
            int off = __popc(m & ((1u << lane) - 1u));
            int p = base + off;
            if (p < CAP) {
                g_cols[r][p] = (unsigned)(c0 + lane) * 16u;   // uint words per row
                g_vals[r][p] = v;
            }
        }
        base += __popc(m);
    }
    if (base > CAP) base = CAP;
    int padded = (base + 15) & ~15;
    if (padded < 16) padded = 16;
    if (padded > CAP) padded = CAP;
    for (int p = base + lane; p < padded; p += 32) {
        g_cols[r][p] = ((unsigned)(r * 7 + p * 13) & (R_ - 1)) * 16u;
        g_vals[r][p] = 0.0f;
    }
    if (lane == 0) g_cnt[r] = padded;

    // reset per-launch mutable state (graph replay safe)
    g_state[0][r * B_ + lane] = __float2half(0.0f);
    if (r < GRID && lane == 0) g_flag[r << 5] = 0u;
}

// ---------------- P2: persistent recurrence ----------------
__global__ void __launch_bounds__(NTHR, 1)
esn_kernel(const float* __restrict__ x,        // [B,T,I]
           const float* __restrict__ win,      // [R,I]
           const float* __restrict__ noise,    // [B,R]
           float* __restrict__ states_out) {   // [B,T,R]
    __shared__ uint2 snnz[RPC][CAP];           // (col*16, val bits)  20 KB
    __shared__ float tile[RPC][B_ + 1];        // staged fp32 outputs for transpose
    __shared__ float xs[B_][4];                // x_t per batch

    const int tid  = threadIdx.x;
    const int w    = tid >> 5;                 // warp = local row
    const int lane = tid & 31;
    const int hsel = lane >> 4;                // 0: even nnz, 1: odd nnz
    const int hl   = lane & 15;                // half-lane -> batch pair (2hl, 2hl+1)
    const int b0   = hl << 1;
    const int b1   = b0 + 1;
    const int rbase = blockIdx.x * RPC;
    const int r = rbase + w;

    // preload sparse row into SMEM (reused for all 1000 steps)
    const int cnt = g_cnt[r];
    for (int k = lane; k < cnt; k += 32)
        snnz[w][k] = make_uint2(g_cols[r][k], __float_as_uint(g_vals[r][k]));

    // per-thread constants (2 batches per thread)
    const float nz0 = noise[(size_t)b0 * R_ + r];
    const float nz1 = noise[(size_t)b1 * R_ + r];
    const float w0 = win[r * 3 + 0];
    const float w1 = win[r * 3 + 1];
    const float w2 = win[r * 3 + 2];

    // stage x for t=0
    if (tid < B_ * I_) {
        int b = tid / 3, i = tid - b * 3;
        xs[b][i] = x[(size_t)b * (T_ * I_) + i];
    }
    __syncthreads();

    const int npairs = cnt >> 1;               // LDGs per row (multiple of 8)

    for (int t = 0; t < T_; t++) {
        const unsigned* cur = (const unsigned*)&g_state[t & 1][0];
        __half2* nxt        = (__half2*)&g_state[(t + 1) & 1][0];

        float ax = fmaf(w0, xs[b0][0], fmaf(w1, xs[b0][1], fmaf(w2, xs[b0][2], nz0)));
        float ay = fmaf(w0, xs[b1][0], fmaf(w1, xs[b1][1], fmaf(w2, xs[b1][2], nz1)));
        // split across even/odd halves: start recurrent accum at 0 on odd half
        float accx = (hsel == 0) ? ax : 0.0f;
        float accy = (hsel == 0) ? ay : 0.0f;

        // ---- software-pipelined gather: 8 LDGs/chunk, each LDG covers 2 nnz ----
        unsigned sA[8]; float vA[8];
        unsigned sB[8]; float vB[8];

        auto load8 = [&](unsigned* s, float* v, int pbase) {
            #pragma unroll
            for (int j = 0; j < 8; j++) {
                uint2 e = snnz[w][((pbase + j) << 1) + hsel];
                v[j] = __uint_as_float(e.y);
                s[j] = __ldcg(cur + e.x + hl);     // L2-only, 4B = 2 fp16 batches
            }
        };
        auto consume8 = [&](const unsigned* s, const float* v) {
            #pragma unroll
            for (int j = 0; j < 8; j++) {
                float2 f = __half22float2(*(const __half2*)&s[j]);
                accx = fmaf(v[j], f.x, accx);
                accy = fmaf(v[j], f.y, accy);
            }
        };

        load8(sA, vA, 0);
        for (int p = 8; p < npairs; p += 16) {
            load8(sB, vB, p);
            consume8(sA, vA);
            if (p + 8 < npairs) load8(sA, vA, p + 8);
            consume8(sB, vB);
        }
        if ((npairs >> 3) & 1) consume8(sA, vA);

        // merge even/odd halves: lanes L and L+16 hold partials for same batches
        accx += __shfl_xor_sync(0xffffffffu, accx, 16);
        accy += __shfl_xor_sync(0xffffffffu, accy, 16);

        float s0 = tanhf(accx);
        float s1 = tanhf(accy);

        if (hsel == 0) {
            nxt[r * (B_ / 2) + hl] = __floats2half2_rn(s0, s1);   // 64B coalesced
            tile[w][b0] = s0;
            tile[w][b1] = s1;
            if (t == T_ - 1) {                   // fp32 final state for outproj
                g_final[r * B_ + b0] = s0;
                g_final[r * B_ + b1] = s1;
            }
        }
        __syncthreads();                         // state + tile visible CTA-wide

        // ---- arrival: make state visible, raise this CTA's flag ----
        if (tid == 0) {
            __threadfence();
            g_flag[blockIdx.x << 5] = (unsigned)(t + 1);
        }

        // ---- off-critical-path work while others arrive ----
        {   // transposed states write: half-warp writes 64B contiguous per batch
            int b  = w + ((lane >> 4) << 4);     // w or w+16
            int rr = lane & 15;
            states_out[(size_t)b * (T_ * R_) + (size_t)t * R_ + rbase + rr] = tile[rr][b];
        }
        if (t + 1 < T_ && tid < B_ * I_) {       // stage x for t+1
            int b = tid / 3, i = tid - b * 3;
            xs[b][i] = x[(size_t)b * (T_ * I_) + (t + 1) * I_ + i];
        }

        // ---- wait: 128 threads poll 128 distinct flag lines ----
        if (tid < GRID) {
            while (g_flag[tid << 5] < (unsigned)(t + 1)) { }
        }
        __syncthreads();
    }
}

// ---------------- P3: output projection ----------------
__global__ void outproj_kernel(const float* __restrict__ wout,  // [O,R]
                               float* __restrict__ out) {       // [B*O]
    __shared__ float red[256];
    int pair = blockIdx.x;            // 0..95
    int b = pair / O_, o = pair - b * O_;

    float sum = 0.0f;
    for (int r = threadIdx.x; r < R_; r += blockDim.x)
        sum += g_final[r * B_ + b] * wout[o * R_ + r];

    red[threadIdx.x] = sum;
    __syncthreads();
    for (int s = 128; s > 0; s >>= 1) {
        if (threadIdx.x < s) red[threadIdx.x] += red[threadIdx.x + s];
        __syncthreads();
    }
    if (threadIdx.x == 0) out[b * O_ + o] = red[0];
}

// ---------------- launch ----------------
extern "C" void kernel_launch(void* const* d_in, const int* in_sizes, int n_in,
                              void* d_out, int out_size) {
    (void)in_sizes; (void)n_in; (void)out_size;
    const float* x     = (const float*)d_in[0];   // [B,T,I]
    const float* win   = (const float*)d_in[1];   // [R,I]
    const float* wres  = (const float*)d_in[2];   // [R,R]
    const float* wout  = (const float*)d_in[3];   // [O,R]
    const float* noise = (const float*)d_in[4];   // [B,R]
    float* out = (float*)d_out;                   // [B*O] then [B,T,R]

    prep_kernel<<<R_, 32>>>(wres);
    esn_kernel<<<GRID, NTHR>>>(x, win, noise, out + B_ * O_);
    outproj_kernel<<<B_ * O_, 256>>>(wout, out);
}